// round 13
// baseline (speedup 1.0000x reference)
#include <cuda_runtime.h>
#include <cuda_fp16.h>

// Shape: [B=2, C=1, D=160, H=192, W=160] fp32, WIN=9 (radius 4), SAME zero pad.
#define Bn 2
#define Dn 160
#define Hn 192
#define Wn 160
#define NV (Bn*Dn*Hn*Wn)            // 9,830,400
#define RW 4
#define WSZ 729.0f

// Fused W+H pass tiling: TH=16, 384 threads, 3 blocks/SM @ 70.1 KB smem.
#define TH 16                        // output rows per block
#define ROWS (TH + 2*RW)             // 24 input rows with halo
#define ISTR 164                     // I/J smem stride (float4-aligned)
#define SSTRH 161                    // W-sum smem stride in halfs (odd)
#define SM_IJ (ROWS * ISTR)          // one input plane (floats)
#define SM_SH (ROWS * SSTRH)         // one W-sum plane (halfs)
#define SMEM_BYTES (2 * SM_IJ * 4 + 5 * SM_SH * 2)   // 70,128 B
#define FT 384                       // fused block threads

// D-pass: 4 columns/thread (uint2), 8 D-segments (40% halo), 128-thr blocks.
#define NCOLQ (Bn*Hn*(Wn/4))         // 15,360 column-quads
#define DSEG 8
#define DSEGLEN (Dn/DSEG)            // 20
#define DPB ((NCOLQ*DSEG)/128)       // 960 blocks

// Intermediate buffer in fp16, channel-major [c][b][d][h][w]. ~98.3 MB.
__device__ __align__(16) __half g_hbuf[5ll * NV];
__device__ float g_part[DPB];
__device__ unsigned g_cnt = 0;       // wraps -> graph-replay safe

// ---------------------------------------------------------------------------
// Fused W+H pass: stage I,J -> W window-sums (products on the fly, fp16
// scratch) -> H window-sum -> fp16 gmem.  384 threads/block, 3840 blocks.
// ---------------------------------------------------------------------------
__global__ __launch_bounds__(FT, 3)
void ncc_fused(const float* __restrict__ I, const float* __restrict__ J) {
    extern __shared__ char smraw[];
    float* __restrict__ sI = (float*)smraw;                  // [ROWS][ISTR]
    float* __restrict__ sJ = sI + SM_IJ;                     // [ROWS][ISTR]
    __half* __restrict__ sS = (__half*)(sJ + SM_IJ);         // [5][ROWS][SSTRH]

    const int t = threadIdx.x;
    const int tile = blockIdx.x;
    const int ht = tile % (Hn / TH);       // 12 tiles along H
    const int slice = tile / (Hn / TH);
    const int d = slice % Dn;
    const int b = slice / Dn;
    const int h0 = ht * TH;

    // Phase A: float4 loads of I,J rows [h0-4, h0+TH+4) into smem.
    for (int idx = t; idx < ROWS * (Wn / 4); idx += FT) {
        const int r = idx / (Wn / 4);
        const int wq = (idx - r * (Wn / 4)) * 4;
        const int hg = h0 - RW + r;
        float4 a = make_float4(0.f, 0.f, 0.f, 0.f);
        float4 c = a;
        if (hg >= 0 && hg < Hn) {
            const size_t o = ((size_t)(b * Dn + d) * Hn + hg) * Wn + wq;
            a = *(const float4*)(I + o);
            c = *(const float4*)(J + o);
        }
        *(float4*)(sI + r * ISTR + wq) = a;
        *(float4*)(sJ + r * ISTR + wq) = c;
    }
    __syncthreads();

    // Phase B: W window-sums for all 5 channels (products on the fly, fp32
    // running sums, fp16 stores). 24 rows x 16 chunks of 10 = 384 jobs.
    {
        const int row = t >> 4;
        const int c0 = (t & 15) * 10;
        const float* __restrict__ rI = sI + row * ISTR;
        const float* __restrict__ rJ = sJ + row * ISTR;
        float s0 = 0.f, s1 = 0.f, s2 = 0.f, s3 = 0.f, s4 = 0.f;
        #pragma unroll
        for (int k = c0 - RW; k <= c0 + RW; ++k) {
            if (k >= 0 && k < Wn) {
                const float a = rI[k], c = rJ[k];
                s0 += a; s1 += c; s2 += a * a; s3 += c * c; s4 += a * c;
            }
        }
        #pragma unroll
        for (int i = 0; i < 10; ++i) {
            const int w = c0 + i;
            sS[0 * SM_SH + row * SSTRH + w] = __float2half_rn(s0);
            sS[1 * SM_SH + row * SSTRH + w] = __float2half_rn(s1);
            sS[2 * SM_SH + row * SSTRH + w] = __float2half_rn(s2);
            sS[3 * SM_SH + row * SSTRH + w] = __float2half_rn(s3);
            sS[4 * SM_SH + row * SSTRH + w] = __float2half_rn(s4);
            if (w + RW + 1 < Wn) {
                const float a = rI[w + RW + 1], c = rJ[w + RW + 1];
                s0 += a; s1 += c; s2 += a * a; s3 += c * c; s4 += a * c;
            }
            if (w - RW >= 0) {
                const float a = rI[w - RW], c = rJ[w - RW];
                s0 -= a; s1 -= c; s2 -= a * a; s3 -= c * c; s4 -= a * c;
            }
        }
    }
    __syncthreads();

    // Phase C: H window-sum per (ch, w) column (fp32 running over fp16 taps).
    for (int job = t; job < 5 * Wn; job += FT) {
        const int w = job % Wn;
        const int ch = job / Wn;
        const __half* __restrict__ col = sS + ch * SM_SH + w;
        float s = 0.f;
        #pragma unroll
        for (int r = 0; r < 2 * RW; ++r) s += __half2float(col[r * SSTRH]);
        __half* __restrict__ ob = g_hbuf + (size_t)ch * NV +
                                  ((size_t)(b * Dn + d) * Hn + h0) * Wn + w;
        #pragma unroll
        for (int o = 0; o < TH; ++o) {
            s += __half2float(col[(o + 2 * RW) * SSTRH]);
            ob[(size_t)o * Wn] = __float2half_rn(s);
            s -= __half2float(col[o * SSTRH]);
        }
    }
}

// ---------------------------------------------------------------------------
// D-pass: running D window-sum (4 columns/thread via LDG.64) + cc +
// reduction + last-block finalize. 960 blocks x 128 threads, 8 segs of 20.
// ---------------------------------------------------------------------------
__device__ __forceinline__ float4 cvt4(uint2 v) {
    const float2 fa = __half22float2(*reinterpret_cast<__half2*>(&v.x));
    const float2 fb = __half22float2(*reinterpret_cast<__half2*>(&v.y));
    return make_float4(fa.x, fa.y, fb.x, fb.y);
}

__global__ void ncc_dpass(float* __restrict__ outp) {
    const int tid = blockIdx.x * blockDim.x + threadIdx.x;   // < 122880
    const int seg = tid / NCOLQ;
    const int cp = tid - seg * NCOLQ;
    const int wq = cp % (Wn / 4);
    int r = cp / (Wn / 4);
    const int h = r % Hn;
    const int b = r / Hn;
    const int d0 = seg * DSEGLEN;

    const size_t dS = (size_t)Hn * (Wn / 4);                 // slice stride (uint2)
    const size_t base = ((size_t)b * Dn) * dS + (size_t)h * (Wn / 4) + wq;
    const uint2* __restrict__ in = (const uint2*)g_hbuf;
    const size_t cNV = (size_t)NV / 4;                       // channel stride (uint2)

    float s[5][4];
    #pragma unroll
    for (int c = 0; c < 5; ++c)
        #pragma unroll
        for (int l = 0; l < 4; ++l) s[c][l] = 0.f;

    #pragma unroll
    for (int d = d0 - RW; d < d0 + RW; ++d) {
        if (d >= 0) {
            const size_t o = base + (size_t)d * dS;
            #pragma unroll
            for (int c = 0; c < 5; ++c) {
                const float4 v = cvt4(in[c * cNV + o]);
                s[c][0] += v.x; s[c][1] += v.y; s[c][2] += v.z; s[c][3] += v.w;
            }
        }
    }

    const float inv = 1.0f / WSZ;
    float acc = 0.f;
    #pragma unroll 2
    for (int dout = d0; dout < d0 + DSEGLEN; ++dout) {
        if (dout + RW < Dn) {
            const size_t o = base + (size_t)(dout + RW) * dS;
            #pragma unroll
            for (int c = 0; c < 5; ++c) {
                const float4 v = cvt4(in[c * cNV + o]);
                s[c][0] += v.x; s[c][1] += v.y; s[c][2] += v.z; s[c][3] += v.w;
            }
        }
        #pragma unroll
        for (int l = 0; l < 4; ++l) {
            const float uI = s[0][l] * inv, uJ = s[1][l] * inv;
            const float cross = s[4][l] - uJ * s[0][l] - uI * s[1][l] + uI * uJ * WSZ;
            const float Iv = s[2][l] - 2.f * uI * s[0][l] + uI * uI * WSZ;
            const float Jv = s[3][l] - 2.f * uJ * s[1][l] + uJ * uJ * WSZ;
            acc += cross * cross / (Iv * Jv + 1e-5f);
        }
        if (dout - RW >= 0) {
            const size_t o = base + (size_t)(dout - RW) * dS;
            #pragma unroll
            for (int c = 0; c < 5; ++c) {
                const float4 v = cvt4(in[c * cNV + o]);
                s[c][0] -= v.x; s[c][1] -= v.y; s[c][2] -= v.z; s[c][3] -= v.w;
            }
        }
    }

    __shared__ float red[128];
    red[threadIdx.x] = acc;
    __syncthreads();
    #pragma unroll
    for (int st = 64; st > 0; st >>= 1) {
        if (threadIdx.x < st) red[threadIdx.x] += red[threadIdx.x + st];
        __syncthreads();
    }

    __shared__ bool is_last;
    if (threadIdx.x == 0) {
        g_part[blockIdx.x] = red[0];
        __threadfence();
        unsigned old = atomicInc(&g_cnt, DPB - 1);
        is_last = (old == DPB - 1);
    }
    __syncthreads();

    if (is_last) {
        const volatile float* vp = g_part;
        double v = 0.0;
        for (int i = threadIdx.x; i < DPB; i += 128) v += (double)vp[i];
        __shared__ double dred[128];
        dred[threadIdx.x] = v;
        __syncthreads();
        #pragma unroll
        for (int st = 64; st > 0; st >>= 1) {
            if (threadIdx.x < st) dred[threadIdx.x] += dred[threadIdx.x + st];
            __syncthreads();
        }
        if (threadIdx.x == 0) outp[0] = (float)(-(dred[0] / (double)NV));
    }
}

extern "C" void kernel_launch(void* const* d_in, const int* in_sizes, int n_in,
                              void* d_out, int out_size) {
    const float* I = (const float*)d_in[0];
    const float* J = (const float*)d_in[1];
    float* out = (float*)d_out;

    cudaFuncSetAttribute(ncc_fused, cudaFuncAttributeMaxDynamicSharedMemorySize,
                         SMEM_BYTES);

    ncc_fused<<<Bn * Dn * (Hn / TH), FT, SMEM_BYTES>>>(I, J);  // 3840 blocks
    ncc_dpass<<<DPB, 128>>>(out);                               // 960 blocks
}

// round 14
// speedup vs baseline: 1.1267x; 1.1267x over previous
#include <cuda_runtime.h>
#include <cuda_fp16.h>

// Shape: [B=2, C=1, D=160, H=192, W=160] fp32, WIN=9 (radius 4), SAME zero pad.
#define Bn 2
#define Dn 160
#define Hn 192
#define Wn 160
#define NV (Bn*Dn*Hn*Wn)            // 9,830,400
#define RW 4
#define WSZ 729.0f

// Fused W+H pass tiling: TH=16, 384 threads, 3 blocks/SM @ 70.1 KB smem.
#define TH 16                        // output rows per block
#define ROWS (TH + 2*RW)             // 24 input rows with halo
#define ISTR 164                     // I/J smem stride (float4-aligned)
#define SSTRH 161                    // W-sum smem stride in halfs (odd)
#define SM_IJ (ROWS * ISTR)          // one input plane (floats)
#define SM_SH (ROWS * SSTRH)         // one W-sum plane (halfs)
#define SMEM_BYTES (2 * SM_IJ * 4 + 5 * SM_SH * 2)   // 70,128 B
#define FT 384                       // fused block threads

// D-pass: 4 columns/thread (uint2), 8 D-segments, software-pipelined loads.
#define NCOLQ (Bn*Hn*(Wn/4))         // 15,360 column-quads
#define DSEG 8
#define DSEGLEN (Dn/DSEG)            // 20
#define DPB ((NCOLQ*DSEG)/128)       // 960 blocks x 128 threads

// Intermediate buffer in fp16, channel-major [c][b][d][h][w]. ~98.3 MB.
__device__ __align__(16) __half g_hbuf[5ll * NV];
__device__ float g_part[DPB];
__device__ unsigned g_cnt = 0;       // wraps -> graph-replay safe

// ---------------------------------------------------------------------------
// Fused W+H pass (unchanged from R13): stage I,J -> W window-sums (products on
// the fly, fp16 scratch) -> H window-sum -> fp16 gmem. 384 thr, 3840 blocks.
// ---------------------------------------------------------------------------
__global__ __launch_bounds__(FT, 3)
void ncc_fused(const float* __restrict__ I, const float* __restrict__ J) {
    extern __shared__ char smraw[];
    float* __restrict__ sI = (float*)smraw;                  // [ROWS][ISTR]
    float* __restrict__ sJ = sI + SM_IJ;                     // [ROWS][ISTR]
    __half* __restrict__ sS = (__half*)(sJ + SM_IJ);         // [5][ROWS][SSTRH]

    const int t = threadIdx.x;
    const int tile = blockIdx.x;
    const int ht = tile % (Hn / TH);
    const int slice = tile / (Hn / TH);
    const int d = slice % Dn;
    const int b = slice / Dn;
    const int h0 = ht * TH;

    for (int idx = t; idx < ROWS * (Wn / 4); idx += FT) {
        const int r = idx / (Wn / 4);
        const int wq = (idx - r * (Wn / 4)) * 4;
        const int hg = h0 - RW + r;
        float4 a = make_float4(0.f, 0.f, 0.f, 0.f);
        float4 c = a;
        if (hg >= 0 && hg < Hn) {
            const size_t o = ((size_t)(b * Dn + d) * Hn + hg) * Wn + wq;
            a = *(const float4*)(I + o);
            c = *(const float4*)(J + o);
        }
        *(float4*)(sI + r * ISTR + wq) = a;
        *(float4*)(sJ + r * ISTR + wq) = c;
    }
    __syncthreads();

    {
        const int row = t >> 4;
        const int c0 = (t & 15) * 10;
        const float* __restrict__ rI = sI + row * ISTR;
        const float* __restrict__ rJ = sJ + row * ISTR;
        float s0 = 0.f, s1 = 0.f, s2 = 0.f, s3 = 0.f, s4 = 0.f;
        #pragma unroll
        for (int k = c0 - RW; k <= c0 + RW; ++k) {
            if (k >= 0 && k < Wn) {
                const float a = rI[k], c = rJ[k];
                s0 += a; s1 += c; s2 += a * a; s3 += c * c; s4 += a * c;
            }
        }
        #pragma unroll
        for (int i = 0; i < 10; ++i) {
            const int w = c0 + i;
            sS[0 * SM_SH + row * SSTRH + w] = __float2half_rn(s0);
            sS[1 * SM_SH + row * SSTRH + w] = __float2half_rn(s1);
            sS[2 * SM_SH + row * SSTRH + w] = __float2half_rn(s2);
            sS[3 * SM_SH + row * SSTRH + w] = __float2half_rn(s3);
            sS[4 * SM_SH + row * SSTRH + w] = __float2half_rn(s4);
            if (w + RW + 1 < Wn) {
                const float a = rI[w + RW + 1], c = rJ[w + RW + 1];
                s0 += a; s1 += c; s2 += a * a; s3 += c * c; s4 += a * c;
            }
            if (w - RW >= 0) {
                const float a = rI[w - RW], c = rJ[w - RW];
                s0 -= a; s1 -= c; s2 -= a * a; s3 -= c * c; s4 -= a * c;
            }
        }
    }
    __syncthreads();

    for (int job = t; job < 5 * Wn; job += FT) {
        const int w = job % Wn;
        const int ch = job / Wn;
        const __half* __restrict__ col = sS + ch * SM_SH + w;
        float s = 0.f;
        #pragma unroll
        for (int r = 0; r < 2 * RW; ++r) s += __half2float(col[r * SSTRH]);
        __half* __restrict__ ob = g_hbuf + (size_t)ch * NV +
                                  ((size_t)(b * Dn + d) * Hn + h0) * Wn + w;
        #pragma unroll
        for (int o = 0; o < TH; ++o) {
            s += __half2float(col[(o + 2 * RW) * SSTRH]);
            ob[(size_t)o * Wn] = __float2half_rn(s);
            s -= __half2float(col[o * SSTRH]);
        }
    }
}

// ---------------------------------------------------------------------------
// D-pass v2: software-pipelined running D window-sum (4 cols/thread, uint2),
// cc + reduction + last-block finalize. 960 blocks x 128 threads.
// ---------------------------------------------------------------------------
__device__ __forceinline__ float4 cvt4(uint2 v) {
    const float2 fa = __half22float2(*reinterpret_cast<__half2*>(&v.x));
    const float2 fb = __half22float2(*reinterpret_cast<__half2*>(&v.y));
    return make_float4(fa.x, fa.y, fb.x, fb.y);
}

__global__ __launch_bounds__(128)
void ncc_dpass(float* __restrict__ outp) {
    const int tid = blockIdx.x * blockDim.x + threadIdx.x;   // < 122880
    const int seg = tid / NCOLQ;
    const int cp = tid - seg * NCOLQ;
    const int wq = cp % (Wn / 4);
    int r = cp / (Wn / 4);
    const int h = r % Hn;
    const int b = r / Hn;
    const int d0 = seg * DSEGLEN;

    const size_t dS = (size_t)Hn * (Wn / 4);                 // slice stride (uint2)
    const size_t base = ((size_t)b * Dn) * dS + (size_t)h * (Wn / 4) + wq;
    const uint2* __restrict__ p0 = (const uint2*)g_hbuf + base;
    const uint2* __restrict__ p1 = p0 + 1 * ((size_t)NV / 4);
    const uint2* __restrict__ p2 = p0 + 2 * ((size_t)NV / 4);
    const uint2* __restrict__ p3 = p0 + 3 * ((size_t)NV / 4);
    const uint2* __restrict__ p4 = p0 + 4 * ((size_t)NV / 4);

    const uint2 Z = make_uint2(0u, 0u);

    float s[5][4];
    #pragma unroll
    for (int c = 0; c < 5; ++c)
        #pragma unroll
        for (int l = 0; l < 4; ++l) s[c][l] = 0.f;

    // Prologue: window [d0-4, d0+4) (bounds-checked, fully unrolled, loads
    // batched before consumption for MLP).
    {
        uint2 pv[2 * RW][5];
        #pragma unroll
        for (int i = 0; i < 2 * RW; ++i) {
            const int d = d0 - RW + i;
            const bool ok = (d >= 0);            // d < Dn always in prologue
            const size_t o = (size_t)(ok ? d : 0) * dS;
            pv[i][0] = ok ? p0[o] : Z;
            pv[i][1] = ok ? p1[o] : Z;
            pv[i][2] = ok ? p2[o] : Z;
            pv[i][3] = ok ? p3[o] : Z;
            pv[i][4] = ok ? p4[o] : Z;
        }
        #pragma unroll
        for (int i = 0; i < 2 * RW; ++i)
            #pragma unroll
            for (int c = 0; c < 5; ++c) {
                const float4 v = cvt4(pv[i][c]);
                s[c][0] += v.x; s[c][1] += v.y; s[c][2] += v.z; s[c][3] += v.w;
            }
    }

    // Main loop: double-buffered prefetch keeps 10 loads in flight per thread.
    uint2 av[5], sv[5];
    {
        const int da = d0 + RW;                  // first add slice
        const bool oka = (da < Dn);
        const size_t oa = (size_t)(oka ? da : 0) * dS;
        av[0] = oka ? p0[oa] : Z; av[1] = oka ? p1[oa] : Z; av[2] = oka ? p2[oa] : Z;
        av[3] = oka ? p3[oa] : Z; av[4] = oka ? p4[oa] : Z;
        const int ds = d0 - RW;                  // first sub slice
        const bool oks = (ds >= 0);
        const size_t os = (size_t)(oks ? ds : 0) * dS;
        sv[0] = oks ? p0[os] : Z; sv[1] = oks ? p1[os] : Z; sv[2] = oks ? p2[os] : Z;
        sv[3] = oks ? p3[os] : Z; sv[4] = oks ? p4[os] : Z;
    }

    const float inv = 1.0f / WSZ;
    float acc = 0.f;
    #pragma unroll 4
    for (int i = 0; i < DSEGLEN; ++i) {
        const int dout = d0 + i;
        // Prefetch next iteration's slices (overshoot on last iter is benign).
        uint2 av2[5], sv2[5];
        {
            const int da = dout + 1 + RW;
            const bool oka = (da < Dn);
            const size_t oa = (size_t)(oka ? da : 0) * dS;
            av2[0] = oka ? p0[oa] : Z; av2[1] = oka ? p1[oa] : Z;
            av2[2] = oka ? p2[oa] : Z; av2[3] = oka ? p3[oa] : Z;
            av2[4] = oka ? p4[oa] : Z;
            const int ds = dout + 1 - RW;
            const bool oks = (ds >= 0);
            const size_t os = (size_t)(oks ? ds : 0) * dS;
            sv2[0] = oks ? p0[os] : Z; sv2[1] = oks ? p1[os] : Z;
            sv2[2] = oks ? p2[os] : Z; sv2[3] = oks ? p3[os] : Z;
            sv2[4] = oks ? p4[os] : Z;
        }

        // Consume current: add slice dout+RW.
        #pragma unroll
        for (int c = 0; c < 5; ++c) {
            const float4 v = cvt4(av[c]);
            s[c][0] += v.x; s[c][1] += v.y; s[c][2] += v.z; s[c][3] += v.w;
        }
        #pragma unroll
        for (int l = 0; l < 4; ++l) {
            const float uI = s[0][l] * inv, uJ = s[1][l] * inv;
            const float cross = s[4][l] - uJ * s[0][l] - uI * s[1][l] + uI * uJ * WSZ;
            const float Iv = s[2][l] - 2.f * uI * s[0][l] + uI * uI * WSZ;
            const float Jv = s[3][l] - 2.f * uJ * s[1][l] + uJ * uJ * WSZ;
            acc += cross * cross / (Iv * Jv + 1e-5f);
        }
        // Subtract slice dout-RW.
        #pragma unroll
        for (int c = 0; c < 5; ++c) {
            const float4 v = cvt4(sv[c]);
            s[c][0] -= v.x; s[c][1] -= v.y; s[c][2] -= v.z; s[c][3] -= v.w;
        }
        #pragma unroll
        for (int c = 0; c < 5; ++c) { av[c] = av2[c]; sv[c] = sv2[c]; }
    }

    __shared__ float red[128];
    red[threadIdx.x] = acc;
    __syncthreads();
    #pragma unroll
    for (int st = 64; st > 0; st >>= 1) {
        if (threadIdx.x < st) red[threadIdx.x] += red[threadIdx.x + st];
        __syncthreads();
    }

    __shared__ bool is_last;
    if (threadIdx.x == 0) {
        g_part[blockIdx.x] = red[0];
        __threadfence();
        unsigned old = atomicInc(&g_cnt, DPB - 1);
        is_last = (old == DPB - 1);
    }
    __syncthreads();

    if (is_last) {
        const volatile float* vp = g_part;
        double v = 0.0;
        for (int i = threadIdx.x; i < DPB; i += 128) v += (double)vp[i];
        __shared__ double dred[128];
        dred[threadIdx.x] = v;
        __syncthreads();
        #pragma unroll
        for (int st = 64; st > 0; st >>= 1) {
            if (threadIdx.x < st) dred[threadIdx.x] += dred[threadIdx.x + st];
            __syncthreads();
        }
        if (threadIdx.x == 0) outp[0] = (float)(-(dred[0] / (double)NV));
    }
}

extern "C" void kernel_launch(void* const* d_in, const int* in_sizes, int n_in,
                              void* d_out, int out_size) {
    const float* I = (const float*)d_in[0];
    const float* J = (const float*)d_in[1];
    float* out = (float*)d_out;

    cudaFuncSetAttribute(ncc_fused, cudaFuncAttributeMaxDynamicSharedMemorySize,
                         SMEM_BYTES);

    ncc_fused<<<Bn * Dn * (Hn / TH), FT, SMEM_BYTES>>>(I, J);  // 3840 blocks
    ncc_dpass<<<DPB, 128>>>(out);                               // 960 blocks
}

// round 15
// speedup vs baseline: 1.3156x; 1.1677x over previous
#include <cuda_runtime.h>
#include <cuda_fp16.h>

// Shape: [B=2, C=1, D=160, H=192, W=160] fp32, WIN=9 (radius 4), SAME zero pad.
#define Bn 2
#define Dn 160
#define Hn 192
#define Wn 160
#define NV (Bn*Dn*Hn*Wn)            // 9,830,400
#define RW 4
#define WSZ 729.0f

// Fused W+H pass tiling: TH=16, 384 threads, 3 blocks/SM @ 70.4 KB smem.
#define TH 16                        // output rows per block
#define ROWS (TH + 2*RW)             // 24 input rows with halo
#define ISTR 164                     // I/J smem stride (float4-aligned)
#define SSTRH 162                    // W-sum smem stride in halfs (EVEN: half2)
#define SM_IJ (ROWS * ISTR)          // one input plane (floats)
#define SM_SH (ROWS * SSTRH)         // one W-sum plane (halfs)
#define SM_SH2 (ROWS * (SSTRH/2))    // one W-sum plane (half2s)
#define SMEM_BYTES (2 * SM_IJ * 4 + 5 * SM_SH * 2)   // 70,368 B
#define FT 384                       // fused block threads

// D-pass: 4 columns/thread (uint2), 8 D-segments, pipelined, half2 sums.
#define NCOLQ (Bn*Hn*(Wn/4))         // 15,360 column-quads
#define DSEG 8
#define DSEGLEN (Dn/DSEG)            // 20
#define DPB ((NCOLQ*DSEG)/128)       // 960 blocks x 128 threads

// Intermediate buffer in fp16, channel-major [c][b][d][h][w]. ~98.3 MB.
__device__ __align__(16) __half g_hbuf[5ll * NV];
__device__ float g_part[DPB];
__device__ unsigned g_cnt = 0;       // wraps -> graph-replay safe

// ---------------------------------------------------------------------------
// Fused W+H pass: stage I,J -> W window-sums (products on the fly, half2
// scratch) -> H window-sum (half2 jobs) -> fp16 gmem. 384 thr, 3840 blocks.
// ---------------------------------------------------------------------------
__global__ __launch_bounds__(FT, 3)
void ncc_fused(const float* __restrict__ I, const float* __restrict__ J) {
    extern __shared__ char smraw[];
    float* __restrict__ sI = (float*)smraw;                  // [ROWS][ISTR]
    float* __restrict__ sJ = sI + SM_IJ;                     // [ROWS][ISTR]
    __half2* __restrict__ sS2 = (__half2*)(sJ + SM_IJ);      // [5][ROWS][SSTRH/2]

    const int t = threadIdx.x;
    const int tile = blockIdx.x;
    const int ht = tile % (Hn / TH);
    const int slice = tile / (Hn / TH);
    const int d = slice % Dn;
    const int b = slice / Dn;
    const int h0 = ht * TH;

    // Phase A: float4 loads of I,J rows [h0-4, h0+TH+4) into smem.
    for (int idx = t; idx < ROWS * (Wn / 4); idx += FT) {
        const int r = idx / (Wn / 4);
        const int wq = (idx - r * (Wn / 4)) * 4;
        const int hg = h0 - RW + r;
        float4 a = make_float4(0.f, 0.f, 0.f, 0.f);
        float4 c = a;
        if (hg >= 0 && hg < Hn) {
            const size_t o = ((size_t)(b * Dn + d) * Hn + hg) * Wn + wq;
            a = *(const float4*)(I + o);
            c = *(const float4*)(J + o);
        }
        *(float4*)(sI + r * ISTR + wq) = a;
        *(float4*)(sJ + r * ISTR + wq) = c;
    }
    __syncthreads();

    // Phase B: W window-sums for all 5 channels (products on the fly, fp32
    // running sums, paired half2 stores). 24 rows x 16 chunks of 10.
    {
        const int row = t >> 4;
        const int c0 = (t & 15) * 10;                 // even
        const float* __restrict__ rI = sI + row * ISTR;
        const float* __restrict__ rJ = sJ + row * ISTR;
        float s0 = 0.f, s1 = 0.f, s2 = 0.f, s3 = 0.f, s4 = 0.f;
        #pragma unroll
        for (int k = c0 - RW; k <= c0 + RW; ++k) {
            if (k >= 0 && k < Wn) {
                const float a = rI[k], c = rJ[k];
                s0 += a; s1 += c; s2 += a * a; s3 += c * c; s4 += a * c;
            }
        }
        __half lo[5];
        #pragma unroll
        for (int i = 0; i < 10; ++i) {
            const int w = c0 + i;
            if ((i & 1) == 0) {
                lo[0] = __float2half_rn(s0); lo[1] = __float2half_rn(s1);
                lo[2] = __float2half_rn(s2); lo[3] = __float2half_rn(s3);
                lo[4] = __float2half_rn(s4);
            } else {
                const int p = row * (SSTRH / 2) + (w >> 1);
                sS2[0 * SM_SH2 + p] = __halves2half2(lo[0], __float2half_rn(s0));
                sS2[1 * SM_SH2 + p] = __halves2half2(lo[1], __float2half_rn(s1));
                sS2[2 * SM_SH2 + p] = __halves2half2(lo[2], __float2half_rn(s2));
                sS2[3 * SM_SH2 + p] = __halves2half2(lo[3], __float2half_rn(s3));
                sS2[4 * SM_SH2 + p] = __halves2half2(lo[4], __float2half_rn(s4));
            }
            if (w + RW + 1 < Wn) {
                const float a = rI[w + RW + 1], c = rJ[w + RW + 1];
                s0 += a; s1 += c; s2 += a * a; s3 += c * c; s4 += a * c;
            }
            if (w - RW >= 0) {
                const float a = rI[w - RW], c = rJ[w - RW];
                s0 -= a; s1 -= c; s2 -= a * a; s3 -= c * c; s4 -= a * c;
            }
        }
    }
    __syncthreads();

    // Phase C: H window-sum, 2 adjacent w per job via half2. 5*80 = 400 jobs.
    for (int job = t; job < 5 * (Wn / 2); job += FT) {
        const int wp = job % (Wn / 2);
        const int ch = job / (Wn / 2);
        const __half2* __restrict__ col = sS2 + ch * SM_SH2 + wp;
        float sa = 0.f, sb = 0.f;
        #pragma unroll
        for (int r = 0; r < 2 * RW; ++r) {
            const float2 v = __half22float2(col[r * (SSTRH / 2)]);
            sa += v.x; sb += v.y;
        }
        __half2* __restrict__ ob = (__half2*)(g_hbuf + (size_t)ch * NV +
                                   ((size_t)(b * Dn + d) * Hn + h0) * Wn) + wp;
        #pragma unroll
        for (int o = 0; o < TH; ++o) {
            const float2 va = __half22float2(col[(o + 2 * RW) * (SSTRH / 2)]);
            sa += va.x; sb += va.y;
            ob[(size_t)o * (Wn / 2)] =
                __halves2half2(__float2half_rn(sa), __float2half_rn(sb));
            const float2 vs = __half22float2(col[o * (SSTRH / 2)]);
            sa -= vs.x; sb -= vs.y;
        }
    }
}

// ---------------------------------------------------------------------------
// D-pass v3: pipelined running D window-sum in HALF2 arithmetic (4 cols/
// thread, uint2), simplified cc, reduction + last-block finalize.
// 960 blocks x 128 threads.
// ---------------------------------------------------------------------------
__device__ __forceinline__ __half2 u2h(unsigned u) {
    return *reinterpret_cast<__half2*>(&u);
}

__global__ __launch_bounds__(128)
void ncc_dpass(float* __restrict__ outp) {
    const int tid = blockIdx.x * blockDim.x + threadIdx.x;   // < 122880
    const int seg = tid / NCOLQ;
    const int cp = tid - seg * NCOLQ;
    const int wq = cp % (Wn / 4);
    int r = cp / (Wn / 4);
    const int h = r % Hn;
    const int b = r / Hn;
    const int d0 = seg * DSEGLEN;

    const size_t dS = (size_t)Hn * (Wn / 4);                 // slice stride (uint2)
    const size_t base = ((size_t)b * Dn) * dS + (size_t)h * (Wn / 4) + wq;
    const uint2* __restrict__ p0 = (const uint2*)g_hbuf + base;
    const uint2* __restrict__ p1 = p0 + 1 * ((size_t)NV / 4);
    const uint2* __restrict__ p2 = p0 + 2 * ((size_t)NV / 4);
    const uint2* __restrict__ p3 = p0 + 3 * ((size_t)NV / 4);
    const uint2* __restrict__ p4 = p0 + 4 * ((size_t)NV / 4);

    const uint2 Z = make_uint2(0u, 0u);

    __half2 sh[5][2];
    #pragma unroll
    for (int c = 0; c < 5; ++c) {
        sh[c][0] = __float2half2_rn(0.f);
        sh[c][1] = __float2half2_rn(0.f);
    }

    // Prologue: window [d0-4, d0+4), loads batched for MLP, half2 adds.
    {
        uint2 pv[2 * RW][5];
        #pragma unroll
        for (int i = 0; i < 2 * RW; ++i) {
            const int d = d0 - RW + i;
            const bool ok = (d >= 0);
            const size_t o = (size_t)(ok ? d : 0) * dS;
            pv[i][0] = ok ? p0[o] : Z;
            pv[i][1] = ok ? p1[o] : Z;
            pv[i][2] = ok ? p2[o] : Z;
            pv[i][3] = ok ? p3[o] : Z;
            pv[i][4] = ok ? p4[o] : Z;
        }
        #pragma unroll
        for (int i = 0; i < 2 * RW; ++i)
            #pragma unroll
            for (int c = 0; c < 5; ++c) {
                sh[c][0] = __hadd2(sh[c][0], u2h(pv[i][c].x));
                sh[c][1] = __hadd2(sh[c][1], u2h(pv[i][c].y));
            }
    }

    // Main loop: double-buffered prefetch (10 loads in flight per thread).
    uint2 av[5], sv[5];
    {
        const int da = d0 + RW;
        const bool oka = (da < Dn);
        const size_t oa = (size_t)(oka ? da : 0) * dS;
        av[0] = oka ? p0[oa] : Z; av[1] = oka ? p1[oa] : Z; av[2] = oka ? p2[oa] : Z;
        av[3] = oka ? p3[oa] : Z; av[4] = oka ? p4[oa] : Z;
        const int ds = d0 - RW;
        const bool oks = (ds >= 0);
        const size_t os = (size_t)(oks ? ds : 0) * dS;
        sv[0] = oks ? p0[os] : Z; sv[1] = oks ? p1[os] : Z; sv[2] = oks ? p2[os] : Z;
        sv[3] = oks ? p3[os] : Z; sv[4] = oks ? p4[os] : Z;
    }

    const float inv = 1.0f / WSZ;
    float acc = 0.f;
    #pragma unroll 4
    for (int i = 0; i < DSEGLEN; ++i) {
        const int dout = d0 + i;
        // Prefetch next iteration's slices.
        uint2 av2[5], sv2[5];
        {
            const int da = dout + 1 + RW;
            const bool oka = (da < Dn);
            const size_t oa = (size_t)(oka ? da : 0) * dS;
            av2[0] = oka ? p0[oa] : Z; av2[1] = oka ? p1[oa] : Z;
            av2[2] = oka ? p2[oa] : Z; av2[3] = oka ? p3[oa] : Z;
            av2[4] = oka ? p4[oa] : Z;
            const int ds = dout + 1 - RW;
            const bool oks = (ds >= 0);
            const size_t os = (size_t)(oks ? ds : 0) * dS;
            sv2[0] = oks ? p0[os] : Z; sv2[1] = oks ? p1[os] : Z;
            sv2[2] = oks ? p2[os] : Z; sv2[3] = oks ? p3[os] : Z;
            sv2[4] = oks ? p4[os] : Z;
        }

        // Add slice dout+RW (half2 SIMD).
        #pragma unroll
        for (int c = 0; c < 5; ++c) {
            sh[c][0] = __hadd2(sh[c][0], u2h(av[c].x));
            sh[c][1] = __hadd2(sh[c][1], u2h(av[c].y));
        }

        // cc for 4 lanes, simplified: cross = s4 - s0*s1/W, Iv = s2 - s0^2/W.
        float s[5][4];
        #pragma unroll
        for (int c = 0; c < 5; ++c) {
            const float2 f0 = __half22float2(sh[c][0]);
            const float2 f1 = __half22float2(sh[c][1]);
            s[c][0] = f0.x; s[c][1] = f0.y; s[c][2] = f1.x; s[c][3] = f1.y;
        }
        #pragma unroll
        for (int l = 0; l < 4; ++l) {
            const float pI = s[0][l] * inv;
            const float qJ = s[1][l] * inv;
            const float cross = s[4][l] - pI * s[1][l];
            const float Iv = s[2][l] - pI * s[0][l];
            const float Jv = s[3][l] - qJ * s[1][l];
            acc += cross * cross / (Iv * Jv + 1e-5f);
        }

        // Subtract slice dout-RW.
        #pragma unroll
        for (int c = 0; c < 5; ++c) {
            sh[c][0] = __hsub2(sh[c][0], u2h(sv[c].x));
            sh[c][1] = __hsub2(sh[c][1], u2h(sv[c].y));
        }
        #pragma unroll
        for (int c = 0; c < 5; ++c) { av[c] = av2[c]; sv[c] = sv2[c]; }
    }

    __shared__ float red[128];
    red[threadIdx.x] = acc;
    __syncthreads();
    #pragma unroll
    for (int st = 64; st > 0; st >>= 1) {
        if (threadIdx.x < st) red[threadIdx.x] += red[threadIdx.x + st];
        __syncthreads();
    }

    __shared__ bool is_last;
    if (threadIdx.x == 0) {
        g_part[blockIdx.x] = red[0];
        __threadfence();
        unsigned old = atomicInc(&g_cnt, DPB - 1);
        is_last = (old == DPB - 1);
    }
    __syncthreads();

    if (is_last) {
        const volatile float* vp = g_part;
        double v = 0.0;
        for (int i = threadIdx.x; i < DPB; i += 128) v += (double)vp[i];
        __shared__ double dred[128];
        dred[threadIdx.x] = v;
        __syncthreads();
        #pragma unroll
        for (int st = 64; st > 0; st >>= 1) {
            if (threadIdx.x < st) dred[threadIdx.x] += dred[threadIdx.x + st];
            __syncthreads();
        }
        if (threadIdx.x == 0) outp[0] = (float)(-(dred[0] / (double)NV));
    }
}

extern "C" void kernel_launch(void* const* d_in, const int* in_sizes, int n_in,
                              void* d_out, int out_size) {
    const float* I = (const float*)d_in[0];
    const float* J = (const float*)d_in[1];
    float* out = (float*)d_out;

    cudaFuncSetAttribute(ncc_fused, cudaFuncAttributeMaxDynamicSharedMemorySize,
                         SMEM_BYTES);

    ncc_fused<<<Bn * Dn * (Hn / TH), FT, SMEM_BYTES>>>(I, J);  // 3840 blocks
    ncc_dpass<<<DPB, 128>>>(out);                               // 960 blocks
}

// round 16
// speedup vs baseline: 1.4410x; 1.0953x over previous
#include <cuda_runtime.h>
#include <cuda_fp16.h>

// Shape: [B=2, C=1, D=160, H=192, W=160] fp32, WIN=9 (radius 4), SAME zero pad.
#define Bn 2
#define Dn 160
#define Hn 192
#define Wn 160
#define NV (Bn*Dn*Hn*Wn)            // 9,830,400
#define RW 4
#define WSZ 729.0f

// Fused W+H pass tiling: TH=16, 384 threads, 3 blocks/SM @ 70.4 KB smem.
#define TH 16
#define ROWS (TH + 2*RW)             // 24
#define ISTR 164
#define SSTRH 162                    // even: half2 scratch
#define SM_IJ (ROWS * ISTR)
#define SM_SH (ROWS * SSTRH)
#define SM_SH2 (ROWS * (SSTRH/2))
#define SMEM_BYTES (2 * SM_IJ * 4 + 5 * SM_SH * 2)   // 70,368 B
#define FT 384

// D-pass: 4 columns/thread (uint2), 8 D-segments, pipelined, half2 sums.
#define NCOLQ (Bn*Hn*(Wn/4))         // 15,360 column-quads
#define DSEG 8
#define DSEGLEN (Dn/DSEG)            // 20
#define DPB ((NCOLQ*DSEG)/128)       // 960 blocks x 128 threads

__device__ __align__(16) __half g_hbuf[5ll * NV];
__device__ float g_part[DPB];
__device__ unsigned g_cnt = 0;       // wraps -> graph-replay safe

// ---------------------------------------------------------------------------
// Fused W+H pass (unchanged from R15).
// ---------------------------------------------------------------------------
__global__ __launch_bounds__(FT, 3)
void ncc_fused(const float* __restrict__ I, const float* __restrict__ J) {
    extern __shared__ char smraw[];
    float* __restrict__ sI = (float*)smraw;
    float* __restrict__ sJ = sI + SM_IJ;
    __half2* __restrict__ sS2 = (__half2*)(sJ + SM_IJ);

    const int t = threadIdx.x;
    const int tile = blockIdx.x;
    const int ht = tile % (Hn / TH);
    const int slice = tile / (Hn / TH);
    const int d = slice % Dn;
    const int b = slice / Dn;
    const int h0 = ht * TH;

    for (int idx = t; idx < ROWS * (Wn / 4); idx += FT) {
        const int r = idx / (Wn / 4);
        const int wq = (idx - r * (Wn / 4)) * 4;
        const int hg = h0 - RW + r;
        float4 a = make_float4(0.f, 0.f, 0.f, 0.f);
        float4 c = a;
        if (hg >= 0 && hg < Hn) {
            const size_t o = ((size_t)(b * Dn + d) * Hn + hg) * Wn + wq;
            a = *(const float4*)(I + o);
            c = *(const float4*)(J + o);
        }
        *(float4*)(sI + r * ISTR + wq) = a;
        *(float4*)(sJ + r * ISTR + wq) = c;
    }
    __syncthreads();

    {
        const int row = t >> 4;
        const int c0 = (t & 15) * 10;
        const float* __restrict__ rI = sI + row * ISTR;
        const float* __restrict__ rJ = sJ + row * ISTR;
        float s0 = 0.f, s1 = 0.f, s2 = 0.f, s3 = 0.f, s4 = 0.f;
        #pragma unroll
        for (int k = c0 - RW; k <= c0 + RW; ++k) {
            if (k >= 0 && k < Wn) {
                const float a = rI[k], c = rJ[k];
                s0 += a; s1 += c; s2 += a * a; s3 += c * c; s4 += a * c;
            }
        }
        __half lo[5];
        #pragma unroll
        for (int i = 0; i < 10; ++i) {
            const int w = c0 + i;
            if ((i & 1) == 0) {
                lo[0] = __float2half_rn(s0); lo[1] = __float2half_rn(s1);
                lo[2] = __float2half_rn(s2); lo[3] = __float2half_rn(s3);
                lo[4] = __float2half_rn(s4);
            } else {
                const int p = row * (SSTRH / 2) + (w >> 1);
                sS2[0 * SM_SH2 + p] = __halves2half2(lo[0], __float2half_rn(s0));
                sS2[1 * SM_SH2 + p] = __halves2half2(lo[1], __float2half_rn(s1));
                sS2[2 * SM_SH2 + p] = __halves2half2(lo[2], __float2half_rn(s2));
                sS2[3 * SM_SH2 + p] = __halves2half2(lo[3], __float2half_rn(s3));
                sS2[4 * SM_SH2 + p] = __halves2half2(lo[4], __float2half_rn(s4));
            }
            if (w + RW + 1 < Wn) {
                const float a = rI[w + RW + 1], c = rJ[w + RW + 1];
                s0 += a; s1 += c; s2 += a * a; s3 += c * c; s4 += a * c;
            }
            if (w - RW >= 0) {
                const float a = rI[w - RW], c = rJ[w - RW];
                s0 -= a; s1 -= c; s2 -= a * a; s3 -= c * c; s4 -= a * c;
            }
        }
    }
    __syncthreads();

    for (int job = t; job < 5 * (Wn / 2); job += FT) {
        const int wp = job % (Wn / 2);
        const int ch = job / (Wn / 2);
        const __half2* __restrict__ col = sS2 + ch * SM_SH2 + wp;
        float sa = 0.f, sb = 0.f;
        #pragma unroll
        for (int r = 0; r < 2 * RW; ++r) {
            const float2 v = __half22float2(col[r * (SSTRH / 2)]);
            sa += v.x; sb += v.y;
        }
        __half2* __restrict__ ob = (__half2*)(g_hbuf + (size_t)ch * NV +
                                   ((size_t)(b * Dn + d) * Hn + h0) * Wn) + wp;
        #pragma unroll
        for (int o = 0; o < TH; ++o) {
            const float2 va = __half22float2(col[(o + 2 * RW) * (SSTRH / 2)]);
            sa += va.x; sb += va.y;
            ob[(size_t)o * (Wn / 2)] =
                __halves2half2(__float2half_rn(sa), __float2half_rn(sb));
            const float2 vs = __half22float2(col[o * (SSTRH / 2)]);
            sa -= vs.x; sb -= vs.y;
        }
    }
}

// ---------------------------------------------------------------------------
// D-pass v4: boundary-peeled, pointer-incremented, fast-div cc.
// 960 blocks x 128 threads; segments 1..6 take the predicate-free fast path.
// ---------------------------------------------------------------------------
__device__ __forceinline__ __half2 u2h(unsigned u) {
    return *reinterpret_cast<__half2*>(&u);
}

__device__ __forceinline__ float cc4(const __half2 sh[5][2], float inv) {
    float s[5][4];
    #pragma unroll
    for (int c = 0; c < 5; ++c) {
        const float2 f0 = __half22float2(sh[c][0]);
        const float2 f1 = __half22float2(sh[c][1]);
        s[c][0] = f0.x; s[c][1] = f0.y; s[c][2] = f1.x; s[c][3] = f1.y;
    }
    float acc = 0.f;
    #pragma unroll
    for (int l = 0; l < 4; ++l) {
        const float pI = s[0][l] * inv;
        const float qJ = s[1][l] * inv;
        const float cross = s[4][l] - pI * s[1][l];
        const float Iv = s[2][l] - pI * s[0][l];
        const float Jv = s[3][l] - qJ * s[1][l];
        acc += __fdividef(cross * cross, Iv * Jv + 1e-5f);
    }
    return acc;
}

__global__ __launch_bounds__(128)
void ncc_dpass(float* __restrict__ outp) {
    const int tid = blockIdx.x * blockDim.x + threadIdx.x;   // < 122880
    const int seg = tid / NCOLQ;
    const int cp = tid - seg * NCOLQ;
    const int wq = cp % (Wn / 4);
    int r = cp / (Wn / 4);
    const int h = r % Hn;
    const int b = r / Hn;
    const int d0 = seg * DSEGLEN;

    const size_t dS = (size_t)Hn * (Wn / 4);                 // slice stride (uint2)
    const size_t base = ((size_t)b * Dn) * dS + (size_t)h * (Wn / 4) + wq;
    const uint2* __restrict__ p0 = (const uint2*)g_hbuf + base;
    const uint2* __restrict__ p1 = p0 + 1 * ((size_t)NV / 4);
    const uint2* __restrict__ p2 = p0 + 2 * ((size_t)NV / 4);
    const uint2* __restrict__ p3 = p0 + 3 * ((size_t)NV / 4);
    const uint2* __restrict__ p4 = p0 + 4 * ((size_t)NV / 4);

    const uint2 Z = make_uint2(0u, 0u);
    const float inv = 1.0f / WSZ;

    __half2 sh[5][2];
    #pragma unroll
    for (int c = 0; c < 5; ++c) {
        sh[c][0] = __float2half2_rn(0.f);
        sh[c][1] = __float2half2_rn(0.f);
    }

    float acc = 0.f;

    if (seg != 0 && seg != DSEG - 1) {
        // ---------------- FAST PATH: no bounds checks anywhere ----------------
        // Prologue window [d0-4, d0+4).
        {
            uint2 pv[2 * RW][5];
            size_t o = (size_t)(d0 - RW) * dS;
            #pragma unroll
            for (int i = 0; i < 2 * RW; ++i, o += dS) {
                pv[i][0] = p0[o]; pv[i][1] = p1[o]; pv[i][2] = p2[o];
                pv[i][3] = p3[o]; pv[i][4] = p4[o];
            }
            #pragma unroll
            for (int i = 0; i < 2 * RW; ++i)
                #pragma unroll
                for (int c = 0; c < 5; ++c) {
                    sh[c][0] = __hadd2(sh[c][0], u2h(pv[i][c].x));
                    sh[c][1] = __hadd2(sh[c][1], u2h(pv[i][c].y));
                }
        }
        size_t oa = (size_t)(d0 + RW) * dS;
        size_t os = (size_t)(d0 - RW) * dS;
        uint2 av[5], sv[5];
        av[0] = p0[oa]; av[1] = p1[oa]; av[2] = p2[oa]; av[3] = p3[oa]; av[4] = p4[oa];
        sv[0] = p0[os]; sv[1] = p1[os]; sv[2] = p2[os]; sv[3] = p3[os]; sv[4] = p4[os];

        #pragma unroll 4
        for (int i = 0; i < DSEGLEN; ++i) {
            oa += dS; os += dS;
            // Prefetch (overshoots segment but stays in-array for interior segs).
            uint2 av2[5], sv2[5];
            av2[0] = p0[oa]; av2[1] = p1[oa]; av2[2] = p2[oa];
            av2[3] = p3[oa]; av2[4] = p4[oa];
            sv2[0] = p0[os]; sv2[1] = p1[os]; sv2[2] = p2[os];
            sv2[3] = p3[os]; sv2[4] = p4[os];

            #pragma unroll
            for (int c = 0; c < 5; ++c) {
                sh[c][0] = __hadd2(sh[c][0], u2h(av[c].x));
                sh[c][1] = __hadd2(sh[c][1], u2h(av[c].y));
            }
            acc += cc4(sh, inv);
            #pragma unroll
            for (int c = 0; c < 5; ++c) {
                sh[c][0] = __hsub2(sh[c][0], u2h(sv[c].x));
                sh[c][1] = __hsub2(sh[c][1], u2h(sv[c].y));
            }
            #pragma unroll
            for (int c = 0; c < 5; ++c) { av[c] = av2[c]; sv[c] = sv2[c]; }
        }
    } else {
        // ---------------- CHECKED PATH: first and last segments ----------------
        {
            uint2 pv[2 * RW][5];
            #pragma unroll
            for (int i = 0; i < 2 * RW; ++i) {
                const int d = d0 - RW + i;
                const bool ok = (d >= 0);
                const size_t o = (size_t)(ok ? d : 0) * dS;
                pv[i][0] = ok ? p0[o] : Z; pv[i][1] = ok ? p1[o] : Z;
                pv[i][2] = ok ? p2[o] : Z; pv[i][3] = ok ? p3[o] : Z;
                pv[i][4] = ok ? p4[o] : Z;
            }
            #pragma unroll
            for (int i = 0; i < 2 * RW; ++i)
                #pragma unroll
                for (int c = 0; c < 5; ++c) {
                    sh[c][0] = __hadd2(sh[c][0], u2h(pv[i][c].x));
                    sh[c][1] = __hadd2(sh[c][1], u2h(pv[i][c].y));
                }
        }
        uint2 av[5], sv[5];
        {
            const int da = d0 + RW;
            const bool oka = (da < Dn);
            const size_t oa = (size_t)(oka ? da : 0) * dS;
            av[0] = oka ? p0[oa] : Z; av[1] = oka ? p1[oa] : Z;
            av[2] = oka ? p2[oa] : Z; av[3] = oka ? p3[oa] : Z;
            av[4] = oka ? p4[oa] : Z;
            const int ds = d0 - RW;
            const bool oks = (ds >= 0);
            const size_t os = (size_t)(oks ? ds : 0) * dS;
            sv[0] = oks ? p0[os] : Z; sv[1] = oks ? p1[os] : Z;
            sv[2] = oks ? p2[os] : Z; sv[3] = oks ? p3[os] : Z;
            sv[4] = oks ? p4[os] : Z;
        }
        #pragma unroll 4
        for (int i = 0; i < DSEGLEN; ++i) {
            const int dout = d0 + i;
            uint2 av2[5], sv2[5];
            {
                const int da = dout + 1 + RW;
                const bool oka = (da < Dn);
                const size_t oa = (size_t)(oka ? da : 0) * dS;
                av2[0] = oka ? p0[oa] : Z; av2[1] = oka ? p1[oa] : Z;
                av2[2] = oka ? p2[oa] : Z; av2[3] = oka ? p3[oa] : Z;
                av2[4] = oka ? p4[oa] : Z;
                const int ds = dout + 1 - RW;
                const bool oks = (ds >= 0);
                const size_t os = (size_t)(oks ? ds : 0) * dS;
                sv2[0] = oks ? p0[os] : Z; sv2[1] = oks ? p1[os] : Z;
                sv2[2] = oks ? p2[os] : Z; sv2[3] = oks ? p3[os] : Z;
                sv2[4] = oks ? p4[os] : Z;
            }
            #pragma unroll
            for (int c = 0; c < 5; ++c) {
                sh[c][0] = __hadd2(sh[c][0], u2h(av[c].x));
                sh[c][1] = __hadd2(sh[c][1], u2h(av[c].y));
            }
            acc += cc4(sh, inv);
            #pragma unroll
            for (int c = 0; c < 5; ++c) {
                sh[c][0] = __hsub2(sh[c][0], u2h(sv[c].x));
                sh[c][1] = __hsub2(sh[c][1], u2h(sv[c].y));
            }
            #pragma unroll
            for (int c = 0; c < 5; ++c) { av[c] = av2[c]; sv[c] = sv2[c]; }
        }
    }

    __shared__ float red[128];
    red[threadIdx.x] = acc;
    __syncthreads();
    #pragma unroll
    for (int st = 64; st > 0; st >>= 1) {
        if (threadIdx.x < st) red[threadIdx.x] += red[threadIdx.x + st];
        __syncthreads();
    }

    __shared__ bool is_last;
    if (threadIdx.x == 0) {
        g_part[blockIdx.x] = red[0];
        __threadfence();
        unsigned old = atomicInc(&g_cnt, DPB - 1);
        is_last = (old == DPB - 1);
    }
    __syncthreads();

    if (is_last) {
        const volatile float* vp = g_part;
        double v = 0.0;
        for (int i = threadIdx.x; i < DPB; i += 128) v += (double)vp[i];
        __shared__ double dred[128];
        dred[threadIdx.x] = v;
        __syncthreads();
        #pragma unroll
        for (int st = 64; st > 0; st >>= 1) {
            if (threadIdx.x < st) dred[threadIdx.x] += dred[threadIdx.x + st];
            __syncthreads();
        }
        if (threadIdx.x == 0) outp[0] = (float)(-(dred[0] / (double)NV));
    }
}

extern "C" void kernel_launch(void* const* d_in, const int* in_sizes, int n_in,
                              void* d_out, int out_size) {
    const float* I = (const float*)d_in[0];
    const float* J = (const float*)d_in[1];
    float* out = (float*)d_out;

    cudaFuncSetAttribute(ncc_fused, cudaFuncAttributeMaxDynamicSharedMemorySize,
                         SMEM_BYTES);

    ncc_fused<<<Bn * Dn * (Hn / TH), FT, SMEM_BYTES>>>(I, J);  // 3840 blocks
    ncc_dpass<<<DPB, 128>>>(out);                               // 960 blocks
}

// round 17
// speedup vs baseline: 1.4820x; 1.0285x over previous
#include <cuda_runtime.h>
#include <cuda_fp16.h>

// Shape: [B=2, C=1, D=160, H=192, W=160] fp32, WIN=9 (radius 4), SAME zero pad.
#define Bn 2
#define Dn 160
#define Hn 192
#define Wn 160
#define NV (Bn*Dn*Hn*Wn)            // 9,830,400
#define RW 4
#define WSZ 729.0f

// Fused W+H pass tiling: TH=16, 384 threads, fp16 staging -> 4 blocks/SM.
#define TH 16
#define ROWS (TH + 2*RW)             // 24
#define ISTRH 164                    // I/J smem stride in halfs (mult of 4)
#define SSTRH 162                    // W-sum smem stride in halfs (even)
#define SM_IJH (ROWS * ISTRH)        // one input plane (halfs)
#define SM_SH (ROWS * SSTRH)
#define SM_SH2 (ROWS * (SSTRH/2))
#define SMEM_BYTES (2 * SM_IJH * 2 + 5 * SM_SH * 2)   // 54,576 B
#define FT 384

// D-pass: 4 columns/thread (uint2), 8 D-segments, pipelined, half2 sums.
#define NCOLQ (Bn*Hn*(Wn/4))         // 15,360 column-quads
#define DSEG 8
#define DSEGLEN (Dn/DSEG)            // 20
#define DPB ((NCOLQ*DSEG)/128)       // 960 blocks x 128 threads

__device__ __align__(16) __half g_hbuf[5ll * NV];
__device__ float g_part[DPB];
__device__ unsigned g_cnt = 0;       // wraps -> graph-replay safe

// ---------------------------------------------------------------------------
// Fused W+H pass: fp16-staged I,J -> W window-sums (products on the fly) ->
// H window-sum (half2) -> fp16 gmem. 384 thr, 3840 blocks, 4 blocks/SM.
// ---------------------------------------------------------------------------
__global__ __launch_bounds__(FT, 4)
void ncc_fused(const float* __restrict__ I, const float* __restrict__ J) {
    extern __shared__ char smraw[];
    __half* __restrict__ sIh = (__half*)smraw;               // [ROWS][ISTRH]
    __half* __restrict__ sJh = sIh + SM_IJH;                 // [ROWS][ISTRH]
    __half2* __restrict__ sS2 = (__half2*)(sJh + SM_IJH);    // [5][ROWS][SSTRH/2]

    const int t = threadIdx.x;
    const int tile = blockIdx.x;
    const int ht = tile % (Hn / TH);
    const int slice = tile / (Hn / TH);
    const int d = slice % Dn;
    const int b = slice / Dn;
    const int h0 = ht * TH;

    // Phase A: float4 loads of I,J rows [h0-4, h0+TH+4), stored as fp16.
    for (int idx = t; idx < ROWS * (Wn / 4); idx += FT) {
        const int r = idx / (Wn / 4);
        const int wq = (idx - r * (Wn / 4)) * 4;
        const int hg = h0 - RW + r;
        float4 a = make_float4(0.f, 0.f, 0.f, 0.f);
        float4 c = a;
        if (hg >= 0 && hg < Hn) {
            const size_t o = ((size_t)(b * Dn + d) * Hn + hg) * Wn + wq;
            a = *(const float4*)(I + o);
            c = *(const float4*)(J + o);
        }
        __half2* __restrict__ di = (__half2*)(sIh + r * ISTRH + wq);
        __half2* __restrict__ dj = (__half2*)(sJh + r * ISTRH + wq);
        di[0] = __floats2half2_rn(a.x, a.y);
        di[1] = __floats2half2_rn(a.z, a.w);
        dj[0] = __floats2half2_rn(c.x, c.y);
        dj[1] = __floats2half2_rn(c.z, c.w);
    }
    __syncthreads();

    // Phase B: W window-sums for all 5 channels (fp16 taps, fp32 running
    // sums, paired half2 stores). 24 rows x 16 chunks of 10 = 384 jobs.
    {
        const int row = t >> 4;
        const int c0 = (t & 15) * 10;                 // even
        const __half* __restrict__ rI = sIh + row * ISTRH;
        const __half* __restrict__ rJ = sJh + row * ISTRH;
        float s0 = 0.f, s1 = 0.f, s2 = 0.f, s3 = 0.f, s4 = 0.f;
        #pragma unroll
        for (int k = c0 - RW; k <= c0 + RW; ++k) {
            if (k >= 0 && k < Wn) {
                const float a = __half2float(rI[k]);
                const float c = __half2float(rJ[k]);
                s0 += a; s1 += c; s2 += a * a; s3 += c * c; s4 += a * c;
            }
        }
        __half lo[5];
        #pragma unroll
        for (int i = 0; i < 10; ++i) {
            const int w = c0 + i;
            if ((i & 1) == 0) {
                lo[0] = __float2half_rn(s0); lo[1] = __float2half_rn(s1);
                lo[2] = __float2half_rn(s2); lo[3] = __float2half_rn(s3);
                lo[4] = __float2half_rn(s4);
            } else {
                const int p = row * (SSTRH / 2) + (w >> 1);
                sS2[0 * SM_SH2 + p] = __halves2half2(lo[0], __float2half_rn(s0));
                sS2[1 * SM_SH2 + p] = __halves2half2(lo[1], __float2half_rn(s1));
                sS2[2 * SM_SH2 + p] = __halves2half2(lo[2], __float2half_rn(s2));
                sS2[3 * SM_SH2 + p] = __halves2half2(lo[3], __float2half_rn(s3));
                sS2[4 * SM_SH2 + p] = __halves2half2(lo[4], __float2half_rn(s4));
            }
            if (w + RW + 1 < Wn) {
                const float a = __half2float(rI[w + RW + 1]);
                const float c = __half2float(rJ[w + RW + 1]);
                s0 += a; s1 += c; s2 += a * a; s3 += c * c; s4 += a * c;
            }
            if (w - RW >= 0) {
                const float a = __half2float(rI[w - RW]);
                const float c = __half2float(rJ[w - RW]);
                s0 -= a; s1 -= c; s2 -= a * a; s3 -= c * c; s4 -= a * c;
            }
        }
    }
    __syncthreads();

    // Phase C: H window-sum, 2 adjacent w per job via half2. 400 jobs.
    for (int job = t; job < 5 * (Wn / 2); job += FT) {
        const int wp = job % (Wn / 2);
        const int ch = job / (Wn / 2);
        const __half2* __restrict__ col = sS2 + ch * SM_SH2 + wp;
        float sa = 0.f, sb = 0.f;
        #pragma unroll
        for (int r = 0; r < 2 * RW; ++r) {
            const float2 v = __half22float2(col[r * (SSTRH / 2)]);
            sa += v.x; sb += v.y;
        }
        __half2* __restrict__ ob = (__half2*)(g_hbuf + (size_t)ch * NV +
                                   ((size_t)(b * Dn + d) * Hn + h0) * Wn) + wp;
        #pragma unroll
        for (int o = 0; o < TH; ++o) {
            const float2 va = __half22float2(col[(o + 2 * RW) * (SSTRH / 2)]);
            sa += va.x; sb += va.y;
            ob[(size_t)o * (Wn / 2)] =
                __halves2half2(__float2half_rn(sa), __float2half_rn(sb));
            const float2 vs = __half22float2(col[o * (SSTRH / 2)]);
            sa -= vs.x; sb -= vs.y;
        }
    }
}

// ---------------------------------------------------------------------------
// D-pass v4 (unchanged from R16): boundary-peeled, pipelined, half2 sums,
// fast-div cc. 960 blocks x 128 threads.
// ---------------------------------------------------------------------------
__device__ __forceinline__ __half2 u2h(unsigned u) {
    return *reinterpret_cast<__half2*>(&u);
}

__device__ __forceinline__ float cc4(const __half2 sh[5][2], float inv) {
    float s[5][4];
    #pragma unroll
    for (int c = 0; c < 5; ++c) {
        const float2 f0 = __half22float2(sh[c][0]);
        const float2 f1 = __half22float2(sh[c][1]);
        s[c][0] = f0.x; s[c][1] = f0.y; s[c][2] = f1.x; s[c][3] = f1.y;
    }
    float acc = 0.f;
    #pragma unroll
    for (int l = 0; l < 4; ++l) {
        const float pI = s[0][l] * inv;
        const float qJ = s[1][l] * inv;
        const float cross = s[4][l] - pI * s[1][l];
        const float Iv = s[2][l] - pI * s[0][l];
        const float Jv = s[3][l] - qJ * s[1][l];
        acc += __fdividef(cross * cross, Iv * Jv + 1e-5f);
    }
    return acc;
}

__global__ __launch_bounds__(128)
void ncc_dpass(float* __restrict__ outp) {
    const int tid = blockIdx.x * blockDim.x + threadIdx.x;
    const int seg = tid / NCOLQ;
    const int cp = tid - seg * NCOLQ;
    const int wq = cp % (Wn / 4);
    int r = cp / (Wn / 4);
    const int h = r % Hn;
    const int b = r / Hn;
    const int d0 = seg * DSEGLEN;

    const size_t dS = (size_t)Hn * (Wn / 4);
    const size_t base = ((size_t)b * Dn) * dS + (size_t)h * (Wn / 4) + wq;
    const uint2* __restrict__ p0 = (const uint2*)g_hbuf + base;
    const uint2* __restrict__ p1 = p0 + 1 * ((size_t)NV / 4);
    const uint2* __restrict__ p2 = p0 + 2 * ((size_t)NV / 4);
    const uint2* __restrict__ p3 = p0 + 3 * ((size_t)NV / 4);
    const uint2* __restrict__ p4 = p0 + 4 * ((size_t)NV / 4);

    const uint2 Z = make_uint2(0u, 0u);
    const float inv = 1.0f / WSZ;

    __half2 sh[5][2];
    #pragma unroll
    for (int c = 0; c < 5; ++c) {
        sh[c][0] = __float2half2_rn(0.f);
        sh[c][1] = __float2half2_rn(0.f);
    }

    float acc = 0.f;

    if (seg != 0 && seg != DSEG - 1) {
        {
            uint2 pv[2 * RW][5];
            size_t o = (size_t)(d0 - RW) * dS;
            #pragma unroll
            for (int i = 0; i < 2 * RW; ++i, o += dS) {
                pv[i][0] = p0[o]; pv[i][1] = p1[o]; pv[i][2] = p2[o];
                pv[i][3] = p3[o]; pv[i][4] = p4[o];
            }
            #pragma unroll
            for (int i = 0; i < 2 * RW; ++i)
                #pragma unroll
                for (int c = 0; c < 5; ++c) {
                    sh[c][0] = __hadd2(sh[c][0], u2h(pv[i][c].x));
                    sh[c][1] = __hadd2(sh[c][1], u2h(pv[i][c].y));
                }
        }
        size_t oa = (size_t)(d0 + RW) * dS;
        size_t os = (size_t)(d0 - RW) * dS;
        uint2 av[5], sv[5];
        av[0] = p0[oa]; av[1] = p1[oa]; av[2] = p2[oa]; av[3] = p3[oa]; av[4] = p4[oa];
        sv[0] = p0[os]; sv[1] = p1[os]; sv[2] = p2[os]; sv[3] = p3[os]; sv[4] = p4[os];

        #pragma unroll 4
        for (int i = 0; i < DSEGLEN; ++i) {
            oa += dS; os += dS;
            uint2 av2[5], sv2[5];
            av2[0] = p0[oa]; av2[1] = p1[oa]; av2[2] = p2[oa];
            av2[3] = p3[oa]; av2[4] = p4[oa];
            sv2[0] = p0[os]; sv2[1] = p1[os]; sv2[2] = p2[os];
            sv2[3] = p3[os]; sv2[4] = p4[os];

            #pragma unroll
            for (int c = 0; c < 5; ++c) {
                sh[c][0] = __hadd2(sh[c][0], u2h(av[c].x));
                sh[c][1] = __hadd2(sh[c][1], u2h(av[c].y));
            }
            acc += cc4(sh, inv);
            #pragma unroll
            for (int c = 0; c < 5; ++c) {
                sh[c][0] = __hsub2(sh[c][0], u2h(sv[c].x));
                sh[c][1] = __hsub2(sh[c][1], u2h(sv[c].y));
            }
            #pragma unroll
            for (int c = 0; c < 5; ++c) { av[c] = av2[c]; sv[c] = sv2[c]; }
        }
    } else {
        {
            uint2 pv[2 * RW][5];
            #pragma unroll
            for (int i = 0; i < 2 * RW; ++i) {
                const int d = d0 - RW + i;
                const bool ok = (d >= 0);
                const size_t o = (size_t)(ok ? d : 0) * dS;
                pv[i][0] = ok ? p0[o] : Z; pv[i][1] = ok ? p1[o] : Z;
                pv[i][2] = ok ? p2[o] : Z; pv[i][3] = ok ? p3[o] : Z;
                pv[i][4] = ok ? p4[o] : Z;
            }
            #pragma unroll
            for (int i = 0; i < 2 * RW; ++i)
                #pragma unroll
                for (int c = 0; c < 5; ++c) {
                    sh[c][0] = __hadd2(sh[c][0], u2h(pv[i][c].x));
                    sh[c][1] = __hadd2(sh[c][1], u2h(pv[i][c].y));
                }
        }
        uint2 av[5], sv[5];
        {
            const int da = d0 + RW;
            const bool oka = (da < Dn);
            const size_t oa = (size_t)(oka ? da : 0) * dS;
            av[0] = oka ? p0[oa] : Z; av[1] = oka ? p1[oa] : Z;
            av[2] = oka ? p2[oa] : Z; av[3] = oka ? p3[oa] : Z;
            av[4] = oka ? p4[oa] : Z;
            const int ds = d0 - RW;
            const bool oks = (ds >= 0);
            const size_t os = (size_t)(oks ? ds : 0) * dS;
            sv[0] = oks ? p0[os] : Z; sv[1] = oks ? p1[os] : Z;
            sv[2] = oks ? p2[os] : Z; sv[3] = oks ? p3[os] : Z;
            sv[4] = oks ? p4[os] : Z;
        }
        #pragma unroll 4
        for (int i = 0; i < DSEGLEN; ++i) {
            const int dout = d0 + i;
            uint2 av2[5], sv2[5];
            {
                const int da = dout + 1 + RW;
                const bool oka = (da < Dn);
                const size_t oa = (size_t)(oka ? da : 0) * dS;
                av2[0] = oka ? p0[oa] : Z; av2[1] = oka ? p1[oa] : Z;
                av2[2] = oka ? p2[oa] : Z; av2[3] = oka ? p3[oa] : Z;
                av2[4] = oka ? p4[oa] : Z;
                const int ds = dout + 1 - RW;
                const bool oks = (ds >= 0);
                const size_t os = (size_t)(oks ? ds : 0) * dS;
                sv2[0] = oks ? p0[os] : Z; sv2[1] = oks ? p1[os] : Z;
                sv2[2] = oks ? p2[os] : Z; sv2[3] = oks ? p3[os] : Z;
                sv2[4] = oks ? p4[os] : Z;
            }
            #pragma unroll
            for (int c = 0; c < 5; ++c) {
                sh[c][0] = __hadd2(sh[c][0], u2h(av[c].x));
                sh[c][1] = __hadd2(sh[c][1], u2h(av[c].y));
            }
            acc += cc4(sh, inv);
            #pragma unroll
            for (int c = 0; c < 5; ++c) {
                sh[c][0] = __hsub2(sh[c][0], u2h(sv[c].x));
                sh[c][1] = __hsub2(sh[c][1], u2h(sv[c].y));
            }
            #pragma unroll
            for (int c = 0; c < 5; ++c) { av[c] = av2[c]; sv[c] = sv2[c]; }
        }
    }

    __shared__ float red[128];
    red[threadIdx.x] = acc;
    __syncthreads();
    #pragma unroll
    for (int st = 64; st > 0; st >>= 1) {
        if (threadIdx.x < st) red[threadIdx.x] += red[threadIdx.x + st];
        __syncthreads();
    }

    __shared__ bool is_last;
    if (threadIdx.x == 0) {
        g_part[blockIdx.x] = red[0];
        __threadfence();
        unsigned old = atomicInc(&g_cnt, DPB - 1);
        is_last = (old == DPB - 1);
    }
    __syncthreads();

    if (is_last) {
        const volatile float* vp = g_part;
        double v = 0.0;
        for (int i = threadIdx.x; i < DPB; i += 128) v += (double)vp[i];
        __shared__ double dred[128];
        dred[threadIdx.x] = v;
        __syncthreads();
        #pragma unroll
        for (int st = 64; st > 0; st >>= 1) {
            if (threadIdx.x < st) dred[threadIdx.x] += dred[threadIdx.x + st];
            __syncthreads();
        }
        if (threadIdx.x == 0) outp[0] = (float)(-(dred[0] / (double)NV));
    }
}

extern "C" void kernel_launch(void* const* d_in, const int* in_sizes, int n_in,
                              void* d_out, int out_size) {
    const float* I = (const float*)d_in[0];
    const float* J = (const float*)d_in[1];
    float* out = (float*)d_out;

    cudaFuncSetAttribute(ncc_fused, cudaFuncAttributeMaxDynamicSharedMemorySize,
                         SMEM_BYTES);

    ncc_fused<<<Bn * Dn * (Hn / TH), FT, SMEM_BYTES>>>(I, J);  // 3840 blocks
    ncc_dpass<<<DPB, 128>>>(out);                               // 960 blocks
}